// round 1
// baseline (speedup 1.0000x reference)
#include <cuda_runtime.h>
#include <cuda_bf16.h>
#include <math.h>

// Problem constants
#define S 2048
#define C 2048
#define H 16
#define D 128
#define FF 8192
#define EPS 1e-6f

// ---------------------------------------------------------------------------
// Scratch (static device globals -- no runtime allocation allowed)
// ---------------------------------------------------------------------------
__device__ float g_xn[S * C];      // rmsnorm1 output
__device__ float g_q[S * C];
__device__ float g_k[S * C];
__device__ float g_v[S * C];
__device__ float g_k2[H * S];      // per-head per-key ||k||^2 (post-RoPE)
__device__ float g_ctx[S * C];
__device__ float g_h[S * C];       // residual 1
__device__ float g_y[S * C];       // rmsnorm2 output
__device__ float g_gate[S * FF];
__device__ float g_up[S * FF];

// ---------------------------------------------------------------------------
// packed f32x2 helpers (FFMA2: 2x fp32 FMA per instruction on sm_103a)
// ---------------------------------------------------------------------------
__device__ __forceinline__ unsigned long long pack_f2(float x, float y) {
    unsigned long long r;
    asm("mov.b64 %0, {%1, %2};" : "=l"(r) : "f"(x), "f"(y));
    return r;
}
__device__ __forceinline__ float2 unpack_f2(unsigned long long u) {
    float2 r;
    asm("mov.b64 {%0, %1}, %2;" : "=f"(r.x), "=f"(r.y) : "l"(u));
    return r;
}
__device__ __forceinline__ void ffma2(unsigned long long& d,
                                      unsigned long long a,
                                      unsigned long long b) {
    asm("fma.rn.f32x2 %0, %1, %2, %0;" : "+l"(d) : "l"(a), "l"(b));
}

// ---------------------------------------------------------------------------
// RMSNorm: out[row] = x[row] * rsqrt(mean(x^2) + eps) * w
// grid = S rows, 256 threads
// ---------------------------------------------------------------------------
__global__ void rmsnorm_kernel(const float* __restrict__ x,
                               const float* __restrict__ w,
                               float* __restrict__ out) {
    const int row = blockIdx.x;
    const float* xr = x + (size_t)row * C;
    float s = 0.f;
    for (int c = threadIdx.x; c < C; c += blockDim.x) {
        float v = xr[c];
        s += v * v;
    }
#pragma unroll
    for (int off = 16; off; off >>= 1) s += __shfl_xor_sync(0xffffffffu, s, off);
    __shared__ float sh[8];
    if ((threadIdx.x & 31) == 0) sh[threadIdx.x >> 5] = s;
    __syncthreads();
    __shared__ float inv_s;
    if (threadIdx.x == 0) {
        float t = 0.f;
#pragma unroll
        for (int i = 0; i < 8; ++i) t += sh[i];
        inv_s = rsqrtf(t * (1.0f / C) + EPS);
    }
    __syncthreads();
    const float inv = inv_s;
    float* orow = out + (size_t)row * C;
    for (int c = threadIdx.x; c < C; c += blockDim.x)
        orow[c] = xr[c] * inv * w[c];
}

// ---------------------------------------------------------------------------
// SGEMM (NT): Cmat[M,N] = A[M,K] * B[N,K]^T (+ addend)
// A,B row-major. 128x128 tile, BK=8, 8x8 per thread, f32x2 packed FMA.
// All dims multiples of 128. 256 threads.
// ---------------------------------------------------------------------------
#define BM 128
#define BN 128
#define BK 8

__global__ __launch_bounds__(256) void sgemm_nt(const float* __restrict__ A,
                                                const float* __restrict__ B,
                                                float* __restrict__ Cmat,
                                                const float* __restrict__ addend,
                                                int M, int N, int K) {
    __shared__ unsigned long long As2[BK][BM];    // (a,a) duplicated pairs: 8KB
    __shared__ __align__(16) float Bs[BK][BN];    // 4KB

    const int tid = threadIdx.x;
    const int m0 = blockIdx.y * BM;
    const int n0 = blockIdx.x * BN;

    // loader mapping: each thread brings one float4 of A and of B per chunk
    const int lr = tid >> 1;          // 0..127
    const int lc = (tid & 1) * 4;     // 0 or 4
    const float* Ap = A + (size_t)(m0 + lr) * K + lc;
    const float* Bp = B + (size_t)(n0 + lr) * K + lc;

    const int tx = tid & 15;          // 0..15 -> n sub-tile
    const int ty = tid >> 4;          // 0..15 -> m sub-tile

    unsigned long long acc[8][4];
#pragma unroll
    for (int i = 0; i < 8; ++i)
#pragma unroll
        for (int j = 0; j < 4; ++j) acc[i][j] = 0ull;

    for (int kk = 0; kk < K; kk += BK) {
        float4 av = *reinterpret_cast<const float4*>(Ap + kk);
        float4 bv = *reinterpret_cast<const float4*>(Bp + kk);
        As2[lc + 0][lr] = pack_f2(av.x, av.x);
        As2[lc + 1][lr] = pack_f2(av.y, av.y);
        As2[lc + 2][lr] = pack_f2(av.z, av.z);
        As2[lc + 3][lr] = pack_f2(av.w, av.w);
        Bs[lc + 0][lr] = bv.x;
        Bs[lc + 1][lr] = bv.y;
        Bs[lc + 2][lr] = bv.z;
        Bs[lc + 3][lr] = bv.w;
        __syncthreads();

#pragma unroll
        for (int k = 0; k < BK; ++k) {
            unsigned long long a2[8];
#pragma unroll
            for (int ii = 0; ii < 8; ++ii) a2[ii] = As2[k][ty * 8 + ii];
            unsigned long long b2[4];
            const unsigned long long* bp =
                reinterpret_cast<const unsigned long long*>(&Bs[k][tx * 8]);
#pragma unroll
            for (int jj = 0; jj < 4; ++jj) b2[jj] = bp[jj];
#pragma unroll
            for (int ii = 0; ii < 8; ++ii)
#pragma unroll
                for (int jj = 0; jj < 4; ++jj) ffma2(acc[ii][jj], a2[ii], b2[jj]);
        }
        __syncthreads();
    }

#pragma unroll
    for (int ii = 0; ii < 8; ++ii) {
        const int row = m0 + ty * 8 + ii;
        float* crow = Cmat + (size_t)row * N + n0 + tx * 8;
        const float* arow =
            addend ? (addend + (size_t)row * N + n0 + tx * 8) : nullptr;
#pragma unroll
        for (int jj = 0; jj < 4; ++jj) {
            float2 vv = unpack_f2(acc[ii][jj]);
            if (arow) {
                vv.x += arow[2 * jj];
                vv.y += arow[2 * jj + 1];
            }
            *reinterpret_cast<float2*>(&crow[2 * jj]) = vv;
        }
    }
}

// ---------------------------------------------------------------------------
// RoPE (in place) on [S, H, D] laid out as [S, C]; optionally emit ||k||^2.
// grid (S, H), 64 threads: thread t handles dims t and t+64.
// ---------------------------------------------------------------------------
__global__ void rope_kernel(float* __restrict__ x,
                            const float* __restrict__ cosb,
                            const float* __restrict__ sinb,
                            float* __restrict__ k2out) {
    const int s = blockIdx.x, h = blockIdx.y, t = threadIdx.x;
    float* row = x + (size_t)s * C + h * D;
    const float x1 = row[t], x2 = row[t + 64];
    const float c1 = cosb[s * D + t], s1 = sinb[s * D + t];
    const float c2 = cosb[s * D + t + 64], s2 = sinb[s * D + t + 64];
    const float o1 = x1 * c1 - x2 * s1;   // rot = [-x2, x1]
    const float o2 = x2 * c2 + x1 * s2;
    row[t] = o1;
    row[t + 64] = o2;
    if (k2out) {
        float ss = o1 * o1 + o2 * o2;
#pragma unroll
        for (int off = 16; off; off >>= 1)
            ss += __shfl_xor_sync(0xffffffffu, ss, off);
        __shared__ float sh[2];
        if ((t & 31) == 0) sh[t >> 5] = ss;
        __syncthreads();
        if (t == 0) k2out[(size_t)h * S + s] = sh[0] + sh[1];
    }
}

// ---------------------------------------------------------------------------
// Flash attention (causal, Gaussian kernel). q^2 term cancels in softmax:
// logit = (q.k)/sqrt(D) - k2/(2 sqrt(D)).
// One warp per query row; 8 warps per block. grid (S/8, H).
// ---------------------------------------------------------------------------
__global__ __launch_bounds__(256) void attn_kernel(const float* __restrict__ q,
                                                   const float* __restrict__ k,
                                                   const float* __restrict__ v,
                                                   const float* __restrict__ k2,
                                                   float* __restrict__ ctx) {
    const int h = blockIdx.y;
    const int i = blockIdx.x * 8 + (threadIdx.x >> 5);
    const int lane = threadIdx.x & 31;
    const float invS = 0.08838834764831845f;  // 1/sqrt(128)
    const float hInv = 0.5f * invS;

    const float* qr = q + (size_t)i * C + h * D;
    const float q0 = qr[lane], q1 = qr[lane + 32];
    const float q2v = qr[lane + 64], q3 = qr[lane + 96];

    const float* kb = k + h * D;
    const float* vb = v + h * D;
    const float* k2b = k2 + (size_t)h * S;

    float m = -1e30f, l = 0.f;
    float a0 = 0.f, a1 = 0.f, a2 = 0.f, a3 = 0.f;

    for (int j = 0; j <= i; ++j) {
        const float* kr = kb + (size_t)j * C;
        float s = q0 * kr[lane] + q1 * kr[lane + 32] + q2v * kr[lane + 64] +
                  q3 * kr[lane + 96];
#pragma unroll
        for (int off = 16; off; off >>= 1)
            s += __shfl_xor_sync(0xffffffffu, s, off);
        const float logit = s * invS - k2b[j] * hInv;
        const float mn = fmaxf(m, logit);
        const float sc = __expf(m - mn);
        const float p = __expf(logit - mn);
        l = l * sc + p;
        const float* vr = vb + (size_t)j * C;
        a0 = a0 * sc + p * vr[lane];
        a1 = a1 * sc + p * vr[lane + 32];
        a2 = a2 * sc + p * vr[lane + 64];
        a3 = a3 * sc + p * vr[lane + 96];
        m = mn;
    }
    const float inv = 1.f / l;
    float* cr = ctx + (size_t)i * C + h * D;
    cr[lane] = a0 * inv;
    cr[lane + 32] = a1 * inv;
    cr[lane + 64] = a2 * inv;
    cr[lane + 96] = a3 * inv;
}

// ---------------------------------------------------------------------------
// SiLU(gate) * up, in place into gate
// ---------------------------------------------------------------------------
__global__ void silu_mul_kernel(float* __restrict__ gate,
                                const float* __restrict__ up, int n) {
    int idx = blockIdx.x * blockDim.x + threadIdx.x;
    if (idx < n) {
        float g = gate[idx];
        float u = up[idx];
        float sg = 1.f / (1.f + __expf(-g));
        gate[idx] = g * sg * u;
    }
}

// ---------------------------------------------------------------------------
// launch
// ---------------------------------------------------------------------------
extern "C" void kernel_launch(void* const* d_in, const int* in_sizes, int n_in,
                              void* d_out, int out_size) {
    const float* hidden = (const float*)d_in[0];
    const float* cosb   = (const float*)d_in[1];
    const float* sinb   = (const float*)d_in[2];
    // d_in[3] = attention_mask: exactly causal, handled analytically
    const float* ln1_w  = (const float*)d_in[4];
    const float* wq     = (const float*)d_in[5];
    const float* wk     = (const float*)d_in[6];
    const float* wv     = (const float*)d_in[7];
    const float* wo     = (const float*)d_in[8];
    const float* ln2_w  = (const float*)d_in[9];
    const float* wgate  = (const float*)d_in[10];
    const float* wup    = (const float*)d_in[11];
    const float* wdown  = (const float*)d_in[12];
    float* out = (float*)d_out;

    float *xn, *q, *k, *v, *k2, *ctx, *hbuf, *y, *gate, *up;
    cudaGetSymbolAddress((void**)&xn, g_xn);
    cudaGetSymbolAddress((void**)&q, g_q);
    cudaGetSymbolAddress((void**)&k, g_k);
    cudaGetSymbolAddress((void**)&v, g_v);
    cudaGetSymbolAddress((void**)&k2, g_k2);
    cudaGetSymbolAddress((void**)&ctx, g_ctx);
    cudaGetSymbolAddress((void**)&hbuf, g_h);
    cudaGetSymbolAddress((void**)&y, g_y);
    cudaGetSymbolAddress((void**)&gate, g_gate);
    cudaGetSymbolAddress((void**)&up, g_up);

    // 1. input RMSNorm
    rmsnorm_kernel<<<S, 256>>>(hidden, ln1_w, xn);

    // 2. Q, K, V projections
    dim3 gqkv(C / BN, S / BM);
    sgemm_nt<<<gqkv, 256>>>(xn, wq, q, nullptr, S, C, C);
    sgemm_nt<<<gqkv, 256>>>(xn, wk, k, nullptr, S, C, C);
    sgemm_nt<<<gqkv, 256>>>(xn, wv, v, nullptr, S, C, C);

    // 3. RoPE (k also emits ||k||^2)
    dim3 grope(S, H);
    rope_kernel<<<grope, 64>>>(q, cosb, sinb, nullptr);
    rope_kernel<<<grope, 64>>>(k, cosb, sinb, k2);

    // 4. attention
    dim3 gattn(S / 8, H);
    attn_kernel<<<gattn, 256>>>(q, k, v, k2, ctx);

    // 5. output projection + residual: h = hidden + ctx @ wo^T
    sgemm_nt<<<gqkv, 256>>>(ctx, wo, hbuf, hidden, S, C, C);

    // 6. post-attn RMSNorm
    rmsnorm_kernel<<<S, 256>>>(hbuf, ln2_w, y);

    // 7. FFN gate & up
    dim3 gff(FF / BN, S / BM);
    sgemm_nt<<<gff, 256>>>(y, wgate, gate, nullptr, S, FF, C);
    sgemm_nt<<<gff, 256>>>(y, wup, up, nullptr, S, FF, C);

    // 8. SiLU(gate) * up
    silu_mul_kernel<<<(S * FF + 255) / 256, 256>>>(gate, up, S * FF);

    // 9. down projection + residual -> final output
    dim3 gdown(C / BN, S / BM);
    sgemm_nt<<<gdown, 256>>>(gate, wdown, out, hbuf, S, C, FF);
}

// round 2
// speedup vs baseline: 1.0026x; 1.0026x over previous
#include <cuda_runtime.h>
#include <cuda_bf16.h>
#include <math.h>

// Problem constants
#define S 2048
#define C 2048
#define H 16
#define D 128
#define FF 8192
#define EPS 1e-6f

// ---------------------------------------------------------------------------
// Scratch (static device globals -- no runtime allocation allowed)
// ---------------------------------------------------------------------------
__device__ float g_xn[S * C];      // rmsnorm1 output
__device__ float g_q[S * C];
__device__ float g_k[S * C];
__device__ float g_v[S * C];
__device__ float g_k2[H * S];      // per-head per-key ||k||^2 (post-RoPE)
__device__ float g_ctx[S * C];
__device__ float g_h[S * C];       // residual 1
__device__ float g_y[S * C];       // rmsnorm2 output
__device__ float g_gate[S * FF];
__device__ float g_up[S * FF];

// ---------------------------------------------------------------------------
// packed f32x2 helpers (FFMA2: 2x fp32 FMA per instruction on sm_103a)
// ---------------------------------------------------------------------------
__device__ __forceinline__ unsigned long long pack_f2(float x, float y) {
    unsigned long long r;
    asm("mov.b64 %0, {%1, %2};" : "=l"(r) : "f"(x), "f"(y));
    return r;
}
__device__ __forceinline__ float2 unpack_f2(unsigned long long u) {
    float2 r;
    asm("mov.b64 {%0, %1}, %2;" : "=f"(r.x), "=f"(r.y) : "l"(u));
    return r;
}
__device__ __forceinline__ void ffma2(unsigned long long& d,
                                      unsigned long long a,
                                      unsigned long long b) {
    asm("fma.rn.f32x2 %0, %1, %2, %0;" : "+l"(d) : "l"(a), "l"(b));
}

// ---------------------------------------------------------------------------
// RMSNorm: out[row] = x[row] * rsqrt(mean(x^2) + eps) * w
// grid = S rows, 256 threads
// ---------------------------------------------------------------------------
__global__ void rmsnorm_kernel(const float* __restrict__ x,
                               const float* __restrict__ w,
                               float* __restrict__ out) {
    const int row = blockIdx.x;
    const float* xr = x + (size_t)row * C;
    float s = 0.f;
    for (int c = threadIdx.x; c < C; c += blockDim.x) {
        float v = xr[c];
        s += v * v;
    }
#pragma unroll
    for (int off = 16; off; off >>= 1) s += __shfl_xor_sync(0xffffffffu, s, off);
    __shared__ float sh[8];
    if ((threadIdx.x & 31) == 0) sh[threadIdx.x >> 5] = s;
    __syncthreads();
    __shared__ float inv_s;
    if (threadIdx.x == 0) {
        float t = 0.f;
#pragma unroll
        for (int i = 0; i < 8; ++i) t += sh[i];
        inv_s = rsqrtf(t * (1.0f / C) + EPS);
    }
    __syncthreads();
    const float inv = inv_s;
    float* orow = out + (size_t)row * C;
    for (int c = threadIdx.x; c < C; c += blockDim.x)
        orow[c] = xr[c] * inv * w[c];
}

// ---------------------------------------------------------------------------
// SGEMM (NT): Cmat[M,N] = A[M,K] * B[N,K]^T (+ addend)
// A,B row-major. 128x128 tile, BK=8, 8x8 per thread, f32x2 packed FMA.
// All dims multiples of 128. 256 threads.
// ---------------------------------------------------------------------------
#define BM 128
#define BN 128
#define BK 8

__global__ __launch_bounds__(256) void sgemm_nt(const float* __restrict__ A,
                                                const float* __restrict__ B,
                                                float* __restrict__ Cmat,
                                                const float* __restrict__ addend,
                                                int M, int N, int K) {
    __shared__ unsigned long long As2[BK][BM];    // (a,a) duplicated pairs: 8KB
    __shared__ __align__(16) float Bs[BK][BN];    // 4KB

    const int tid = threadIdx.x;
    const int m0 = blockIdx.y * BM;
    const int n0 = blockIdx.x * BN;

    // loader mapping: each thread brings one float4 of A and of B per chunk
    const int lr = tid >> 1;          // 0..127
    const int lc = (tid & 1) * 4;     // 0 or 4
    const float* Ap = A + (size_t)(m0 + lr) * K + lc;
    const float* Bp = B + (size_t)(n0 + lr) * K + lc;

    const int tx = tid & 15;          // 0..15 -> n sub-tile
    const int ty = tid >> 4;          // 0..15 -> m sub-tile

    unsigned long long acc[8][4];
#pragma unroll
    for (int i = 0; i < 8; ++i)
#pragma unroll
        for (int j = 0; j < 4; ++j) acc[i][j] = 0ull;

    for (int kk = 0; kk < K; kk += BK) {
        float4 av = *reinterpret_cast<const float4*>(Ap + kk);
        float4 bv = *reinterpret_cast<const float4*>(Bp + kk);
        As2[lc + 0][lr] = pack_f2(av.x, av.x);
        As2[lc + 1][lr] = pack_f2(av.y, av.y);
        As2[lc + 2][lr] = pack_f2(av.z, av.z);
        As2[lc + 3][lr] = pack_f2(av.w, av.w);
        Bs[lc + 0][lr] = bv.x;
        Bs[lc + 1][lr] = bv.y;
        Bs[lc + 2][lr] = bv.z;
        Bs[lc + 3][lr] = bv.w;
        __syncthreads();

#pragma unroll
        for (int k = 0; k < BK; ++k) {
            unsigned long long a2[8];
#pragma unroll
            for (int ii = 0; ii < 8; ++ii) a2[ii] = As2[k][ty * 8 + ii];
            unsigned long long b2[4];
            const unsigned long long* bp =
                reinterpret_cast<const unsigned long long*>(&Bs[k][tx * 8]);
#pragma unroll
            for (int jj = 0; jj < 4; ++jj) b2[jj] = bp[jj];
#pragma unroll
            for (int ii = 0; ii < 8; ++ii)
#pragma unroll
                for (int jj = 0; jj < 4; ++jj) ffma2(acc[ii][jj], a2[ii], b2[jj]);
        }
        __syncthreads();
    }

#pragma unroll
    for (int ii = 0; ii < 8; ++ii) {
        const int row = m0 + ty * 8 + ii;
        float* crow = Cmat + (size_t)row * N + n0 + tx * 8;
        const float* arow =
            addend ? (addend + (size_t)row * N + n0 + tx * 8) : nullptr;
#pragma unroll
        for (int jj = 0; jj < 4; ++jj) {
            float2 vv = unpack_f2(acc[ii][jj]);
            if (arow) {
                vv.x += arow[2 * jj];
                vv.y += arow[2 * jj + 1];
            }
            *reinterpret_cast<float2*>(&crow[2 * jj]) = vv;
        }
    }
}

// ---------------------------------------------------------------------------
// RoPE (in place) on [S, H, D] laid out as [S, C]; optionally emit ||k||^2.
// grid (S, H), 64 threads: thread t handles dims t and t+64.
// ---------------------------------------------------------------------------
__global__ void rope_kernel(float* __restrict__ x,
                            const float* __restrict__ cosb,
                            const float* __restrict__ sinb,
                            float* __restrict__ k2out) {
    const int s = blockIdx.x, h = blockIdx.y, t = threadIdx.x;
    float* row = x + (size_t)s * C + h * D;
    const float x1 = row[t], x2 = row[t + 64];
    const float c1 = cosb[s * D + t], s1 = sinb[s * D + t];
    const float c2 = cosb[s * D + t + 64], s2 = sinb[s * D + t + 64];
    const float o1 = x1 * c1 - x2 * s1;   // rot = [-x2, x1]
    const float o2 = x2 * c2 + x1 * s2;
    row[t] = o1;
    row[t + 64] = o2;
    if (k2out) {
        float ss = o1 * o1 + o2 * o2;
#pragma unroll
        for (int off = 16; off; off >>= 1)
            ss += __shfl_xor_sync(0xffffffffu, ss, off);
        __shared__ float sh[2];
        if ((t & 31) == 0) sh[t >> 5] = ss;
        __syncthreads();
        if (t == 0) k2out[(size_t)h * S + s] = sh[0] + sh[1];
    }
}

// ---------------------------------------------------------------------------
// Flash attention (causal, Gaussian kernel). q^2 term cancels in softmax:
// logit = (q.k)/sqrt(D) - k2/(2 sqrt(D)).
// One warp per query row; 8 warps per block. grid (S/8, H).
// ---------------------------------------------------------------------------
__global__ __launch_bounds__(256) void attn_kernel(const float* __restrict__ q,
                                                   const float* __restrict__ k,
                                                   const float* __restrict__ v,
                                                   const float* __restrict__ k2,
                                                   float* __restrict__ ctx) {
    const int h = blockIdx.y;
    const int i = blockIdx.x * 8 + (threadIdx.x >> 5);
    const int lane = threadIdx.x & 31;
    const float invS = 0.08838834764831845f;  // 1/sqrt(128)
    const float hInv = 0.5f * invS;

    const float* qr = q + (size_t)i * C + h * D;
    const float q0 = qr[lane], q1 = qr[lane + 32];
    const float q2v = qr[lane + 64], q3 = qr[lane + 96];

    const float* kb = k + h * D;
    const float* vb = v + h * D;
    const float* k2b = k2 + (size_t)h * S;

    float m = -1e30f, l = 0.f;
    float a0 = 0.f, a1 = 0.f, a2 = 0.f, a3 = 0.f;

    for (int j = 0; j <= i; ++j) {
        const float* kr = kb + (size_t)j * C;
        float s = q0 * kr[lane] + q1 * kr[lane + 32] + q2v * kr[lane + 64] +
                  q3 * kr[lane + 96];
#pragma unroll
        for (int off = 16; off; off >>= 1)
            s += __shfl_xor_sync(0xffffffffu, s, off);
        const float logit = s * invS - k2b[j] * hInv;
        const float mn = fmaxf(m, logit);
        const float sc = __expf(m - mn);
        const float p = __expf(logit - mn);
        l = l * sc + p;
        const float* vr = vb + (size_t)j * C;
        a0 = a0 * sc + p * vr[lane];
        a1 = a1 * sc + p * vr[lane + 32];
        a2 = a2 * sc + p * vr[lane + 64];
        a3 = a3 * sc + p * vr[lane + 96];
        m = mn;
    }
    const float inv = 1.f / l;
    float* cr = ctx + (size_t)i * C + h * D;
    cr[lane] = a0 * inv;
    cr[lane + 32] = a1 * inv;
    cr[lane + 64] = a2 * inv;
    cr[lane + 96] = a3 * inv;
}

// ---------------------------------------------------------------------------
// SiLU(gate) * up, in place into gate
// ---------------------------------------------------------------------------
__global__ void silu_mul_kernel(float* __restrict__ gate,
                                const float* __restrict__ up, int n) {
    int idx = blockIdx.x * blockDim.x + threadIdx.x;
    if (idx < n) {
        float g = gate[idx];
        float u = up[idx];
        float sg = 1.f / (1.f + __expf(-g));
        gate[idx] = g * sg * u;
    }
}

// ---------------------------------------------------------------------------
// launch
// ---------------------------------------------------------------------------
extern "C" void kernel_launch(void* const* d_in, const int* in_sizes, int n_in,
                              void* d_out, int out_size) {
    const float* hidden = (const float*)d_in[0];
    const float* cosb   = (const float*)d_in[1];
    const float* sinb   = (const float*)d_in[2];
    // d_in[3] = attention_mask: exactly causal, handled analytically
    const float* ln1_w  = (const float*)d_in[4];
    const float* wq     = (const float*)d_in[5];
    const float* wk     = (const float*)d_in[6];
    const float* wv     = (const float*)d_in[7];
    const float* wo     = (const float*)d_in[8];
    const float* ln2_w  = (const float*)d_in[9];
    const float* wgate  = (const float*)d_in[10];
    const float* wup    = (const float*)d_in[11];
    const float* wdown  = (const float*)d_in[12];
    float* out = (float*)d_out;

    float *xn, *q, *k, *v, *k2, *ctx, *hbuf, *y, *gate, *up;
    cudaGetSymbolAddress((void**)&xn, g_xn);
    cudaGetSymbolAddress((void**)&q, g_q);
    cudaGetSymbolAddress((void**)&k, g_k);
    cudaGetSymbolAddress((void**)&v, g_v);
    cudaGetSymbolAddress((void**)&k2, g_k2);
    cudaGetSymbolAddress((void**)&ctx, g_ctx);
    cudaGetSymbolAddress((void**)&hbuf, g_h);
    cudaGetSymbolAddress((void**)&y, g_y);
    cudaGetSymbolAddress((void**)&gate, g_gate);
    cudaGetSymbolAddress((void**)&up, g_up);

    // 1. input RMSNorm
    rmsnorm_kernel<<<S, 256>>>(hidden, ln1_w, xn);

    // 2. Q, K, V projections
    dim3 gqkv(C / BN, S / BM);
    sgemm_nt<<<gqkv, 256>>>(xn, wq, q, nullptr, S, C, C);
    sgemm_nt<<<gqkv, 256>>>(xn, wk, k, nullptr, S, C, C);
    sgemm_nt<<<gqkv, 256>>>(xn, wv, v, nullptr, S, C, C);

    // 3. RoPE (k also emits ||k||^2)
    dim3 grope(S, H);
    rope_kernel<<<grope, 64>>>(q, cosb, sinb, nullptr);
    rope_kernel<<<grope, 64>>>(k, cosb, sinb, k2);

    // 4. attention
    dim3 gattn(S / 8, H);
    attn_kernel<<<gattn, 256>>>(q, k, v, k2, ctx);

    // 5. output projection + residual: h = hidden + ctx @ wo^T
    sgemm_nt<<<gqkv, 256>>>(ctx, wo, hbuf, hidden, S, C, C);

    // 6. post-attn RMSNorm
    rmsnorm_kernel<<<S, 256>>>(hbuf, ln2_w, y);

    // 7. FFN gate & up
    dim3 gff(FF / BN, S / BM);
    sgemm_nt<<<gff, 256>>>(y, wgate, gate, nullptr, S, FF, C);
    sgemm_nt<<<gff, 256>>>(y, wup, up, nullptr, S, FF, C);

    // 8. SiLU(gate) * up
    silu_mul_kernel<<<(S * FF + 255) / 256, 256>>>(gate, up, S * FF);

    // 9. down projection + residual -> final output
    dim3 gdown(C / BN, S / BM);
    sgemm_nt<<<gdown, 256>>>(gate, wdown, out, hbuf, S, C, FF);
}